// round 17
// baseline (speedup 1.0000x reference)
#include <cuda_runtime.h>

#define NX 1024
#define NY 1024
#define NBATCH 8
#define CH (1024*1024)
#define NBLOCKS (NY*NBATCH)     // 8192
#define NPTS 8388608.0

// Physics constants
#define PR     0.71f
#define RA_PR  710.0f
#define HA2_PR 71.0f
#define PR_DA  7.1f
#define DIFF_C 1.6666666666666667f
#define QQ     0.1f
#define DTINV  (1.0f/0.01f)

__device__ double   g_acc;       // exchanged to 0 by last CTA each call -> replay-safe
__device__ unsigned g_count = 0; // atomicInc wraps to 0 on last CTA -> replay-safe

// tgrad along x at global index i, window W[12] covers x0-4 .. x0+7, center at W[j+4]
__device__ __forceinline__ float d1x(const float* W, int j, int i) {
    if (i == 0)      return W[5] - W[4];
    if (i == NX - 1) return W[j + 4] - W[j + 3];
    return 0.5f * (W[j + 5] - W[j + 3]);
}

__device__ __forceinline__ float d2x(const float* W, int j, int i) {
    if (i == 0)      return 0.5f * W[6] - W[5] + 0.5f * W[4];
    if (i == 1)      return 0.25f * W[7] - 0.75f * W[5] + 0.5f * W[4];
    if (i == NX - 2) return 0.5f * W[j + 5] - 0.75f * W[j + 4] + 0.25f * W[j + 2];
    if (i == NX - 1) return 0.5f * W[j + 4] - W[j + 3] + 0.5f * W[j + 2];
    return 0.25f * (W[j + 6] - 2.0f * W[j + 4] + W[j + 2]);
}

__device__ __forceinline__ void load_window(const float* __restrict__ row, int tid, int x0, float* W) {
    float4 c = *(const float4*)(row + x0);
    W[4] = c.x; W[5] = c.y; W[6] = c.z; W[7] = c.w;
    if (tid > 0) {
        float4 l = *(const float4*)(row + x0 - 4);
        W[0] = l.x; W[1] = l.y; W[2] = l.z; W[3] = l.w;
    } else { W[0] = W[1] = W[2] = W[3] = 0.0f; }
    if (tid < 255) {
        float4 r = *(const float4*)(row + x0 + 4);
        W[8] = r.x; W[9] = r.y; W[10] = r.z; W[11] = r.w;
    } else { W[8] = W[9] = W[10] = W[11] = 0.0f; }
}

struct Deriv { float v[4], dx[4], dy[4], dxx[4], dyy[4]; };

__device__ __forceinline__ void full_derivs(
    const float* __restrict__ ch, int tid, int y, int x0,
    int rM, int rP, float s1,
    int rA, int rB, float cA, float cC, float cB,
    Deriv& d)
{
    float W[12];
    load_window(ch + (size_t)y * NX, tid, x0, W);
    float4 m  = *(const float4*)(ch + (size_t)rM * NX + x0);
    float4 p  = *(const float4*)(ch + (size_t)rP * NX + x0);
    float4 a  = *(const float4*)(ch + (size_t)rA * NX + x0);
    float4 bb = *(const float4*)(ch + (size_t)rB * NX + x0);
    const float* M  = (const float*)&m;  const float* P_ = (const float*)&p;
    const float* A  = (const float*)&a;  const float* B_ = (const float*)&bb;
#pragma unroll
    for (int j = 0; j < 4; j++) {
        int i = x0 + j;
        d.v[j]   = W[j + 4];
        d.dx[j]  = d1x(W, j, i);
        d.dxx[j] = d2x(W, j, i);
        d.dy[j]  = s1 * (P_[j] - M[j]);
        d.dyy[j] = cA * A[j] + cC * W[j + 4] + cB * B_[j];
    }
}

__global__ __launch_bounds__(256, 5)
void physics_loss_kernel(const float* __restrict__ fno, const float* __restrict__ fne,
                         float* __restrict__ out)
{
    const int tid = threadIdx.x;
    const int y   = blockIdx.x;
    const int b   = blockIdx.y;
    const int x0  = tid * 4;

    const int   rM = (y > 0) ? y - 1 : 0;
    const int   rP = (y < NY - 1) ? y + 1 : NY - 1;
    const float s1 = (y == 0 || y == NY - 1) ? 1.0f : 0.5f;

    int rA, rB; float cA, cC, cB;
    if      (y == 0)      { rA = 2;      cA = 0.5f;  cC = 0.5f;   rB = 1;      cB = -1.0f; }
    else if (y == 1)      { rA = 0;      cA = 0.5f;  cC = -0.75f; rB = 3;      cB = 0.25f; }
    else if (y == NY - 2) { rA = NY - 4; cA = 0.25f; cC = -0.75f; rB = NY - 1; cB = 0.5f;  }
    else if (y == NY - 1) { rA = NY - 3; cA = 0.5f;  cC = 0.5f;   rB = NY - 2; cB = -1.0f; }
    else                  { rA = y - 2;  cA = 0.25f; cC = -0.5f;  rB = y + 2;  cB = 0.25f; }

    const size_t base = (size_t)b * 4 * CH;
    const size_t rowo = (size_t)y * NX + x0;

    float acc = 0.0f;

    // ---- P pass first: pdx, pdy ----
    float pdx[4], pdy[4];
    {
        const float* Pc = fne + base + 3 * (size_t)CH;
        float W[12];
        load_window(Pc + (size_t)y * NX, tid, x0, W);
        float4 m = *(const float4*)(Pc + (size_t)rM * NX + x0);
        float4 p = *(const float4*)(Pc + (size_t)rP * NX + x0);
        const float* M = (const float*)&m; const float* P_ = (const float*)&p;
#pragma unroll
        for (int j = 0; j < 4; j++) {
            pdx[j] = d1x(W, j, x0 + j);
            pdy[j] = s1 * (P_[j] - M[j]);
        }
    }

    float4 uo4 = *(const float4*)(fno + base + 0 * (size_t)CH + rowo);
    float4 vo4 = *(const float4*)(fno + base + 1 * (size_t)CH + rowo);
    float Uo[4] = {uo4.x, uo4.y, uo4.z, uo4.w};
    float Vo[4] = {vo4.x, vo4.y, vo4.z, vo4.w};

    float cont[4], resy[4];

    Deriv D;
    // ---- U pass ----
    full_derivs(fne + base + 0 * (size_t)CH, tid, y, x0, rM, rP, s1, rA, rB, cA, cC, cB, D);
#pragma unroll
    for (int j = 0; j < 4; j++) {
        float Un = D.v[j];
        float resx = (Un - Uo[j]) * DTINV + Un * D.dx[j] + Vo[j] * D.dy[j]
                     + pdx[j] - PR * (D.dxx[j] + D.dyy[j]) + PR_DA * Un;
        acc += resx * resx;
        cont[j] = D.dx[j];
    }
    // ---- V pass ----
    full_derivs(fne + base + 1 * (size_t)CH, tid, y, x0, rM, rP, s1, rA, rB, cA, cC, cB, D);
#pragma unroll
    for (int j = 0; j < 4; j++) {
        float Vn = D.v[j];
        float cj = cont[j] + D.dy[j];
        acc += cj * cj;
        resy[j] = (Vn - Vo[j]) * DTINV + Uo[j] * D.dx[j] + Vn * D.dy[j]
                  + pdy[j] - PR * (D.dxx[j] + D.dyy[j]) + (HA2_PR + PR_DA) * Vn;
    }
    // ---- T pass ----
    full_derivs(fne + base + 2 * (size_t)CH, tid, y, x0, rM, rP, s1, rA, rB, cA, cC, cB, D);
    {
        float4 to4 = *(const float4*)(fno + base + 2 * (size_t)CH + rowo);
        const float* To = (const float*)&to4;
#pragma unroll
        for (int j = 0; j < 4; j++) {
            float Tn = D.v[j];
            float ry = resy[j] - RA_PR * Tn;
            acc += ry * ry;
            float rest = (Tn - To[j]) * DTINV + Uo[j] * D.dx[j] + Vo[j] * D.dy[j]
                         - DIFF_C * (D.dxx[j] + D.dyy[j]) - QQ * Tn;
            acc += rest * rest;
        }
    }

    // warp + block reduce, one atomicAdd per CTA
#pragma unroll
    for (int o = 16; o > 0; o >>= 1) acc += __shfl_xor_sync(0xFFFFFFFFu, acc, o);

    __shared__ float ws[8];
    if ((tid & 31) == 0) ws[tid >> 5] = acc;
    __syncthreads();
    if (tid == 0) {
        float s = 0.0f;
#pragma unroll
        for (int k = 0; k < 8; k++) s += ws[k];
        atomicAdd(&g_acc, (double)s);
        // release-inc: orders this CTA's add before the count bump.
        // NO loop, NO extra state — the R10 regression came from the big
        // fused reduce loop, not the ordering op (R11 control).
        unsigned prev;
        asm volatile("atom.release.gpu.global.inc.u32 %0, [%1], %2;"
                     : "=r"(prev)
                     : "l"(&g_count), "r"((unsigned)(NBLOCKS - 1))
                     : "memory");
        if (prev == NBLOCKS - 1) {
            // acq_rel exchange: acquires all released adds, reads the total,
            // and resets g_acc to 0 for the next graph replay — one op.
            double total;
            asm volatile("atom.acq_rel.gpu.global.exch.b64 %0, [%1], %2;"
                         : "=d"(total)
                         : "l"(&g_acc), "d"(0.0)
                         : "memory");
            double t = total * 1e-4 / NPTS;
            if (t < 1e-10) t = 1e-10;
            if (t > 1.0)   t = 1.0;
            out[0] = (float)t;
        }
    }
}

extern "C" void kernel_launch(void* const* d_in, const int* in_sizes, int n_in,
                              void* d_out, int out_size)
{
    const float* f_now  = (const float*)d_in[0];
    const float* f_next = (const float*)d_in[1];

    dim3 grid(NY, NBATCH);
    physics_loss_kernel<<<grid, 256>>>(f_now, f_next, (float*)d_out);
}